// round 14
// baseline (speedup 1.0000x reference)
#include <cuda_runtime.h>
#include <cuda_fp16.h>
#include <cstdint>
#include <cstddef>

// Problem sizes (fixed)
#define BB 4
#define TT 4096
#define CC 1024
#define MM (BB * TT)          // 16384
#define BTC (BB * TT * CC)    // 16,777,216
#define NCH 128               // scan chunks along T
#define CLEN (TT / NCH)       // 32
#define NBC (BB * CC)         // 4096
#define WSZ (CC * CC)         // 1,048,576
#define CP2 (CC / 2)          // 512 channel pairs

// ---------------------------------------------------------------------------
// Scratch in device globals (no cudaMalloc allowed).
// ---------------------------------------------------------------------------
__device__ __align__(16) uint32_t g_k16[BTC / 2];
__device__ __align__(16) uint32_t g_v16[BTC / 2];
__device__ __align__(16) uint32_t g_r16[BTC / 2];
__device__ __align__(16) uint32_t g_x16[BTC / 2];     // permuted fp16 x
__device__ __align__(16) uint32_t g_wkv16[BTC / 2];   // permuted fp16 (r*wkv)
__device__ __align__(16) uint32_t g_wk16[WSZ / 2], g_wv16[WSZ / 2],
                                  g_wr16[WSZ / 2], g_wo16[WSZ / 2];
__device__ float g_saa[NCH][NBC], g_sbb[NCH][NBC], g_spp[NCH][NBC];
__device__ float g_iaa[NCH][NBC], g_ibb[NCH][NBC], g_ipp[NCH][NBC];

// ---------------------------------------------------------------------------
// Helpers
// ---------------------------------------------------------------------------
__device__ __forceinline__ uint32_t smem_u32(const void* p) {
    return (uint32_t)__cvta_generic_to_shared(p);
}
__device__ __forceinline__ void cp16(uint32_t smem_dst, const void* gmem_src) {
    asm volatile("cp.async.cg.shared.global [%0], [%1], 16;\n" :: "r"(smem_dst), "l"(gmem_src));
}
__device__ __forceinline__ void cp_commit() { asm volatile("cp.async.commit_group;\n"); }
template<int N>
__device__ __forceinline__ void cp_wait() { asm volatile("cp.async.wait_group %0;\n" :: "n"(N)); }

__device__ __forceinline__ uint32_t pack_h2(float lo, float hi) {
    const __half2 h = __floats2half2_rn(lo, hi);   // lo -> low 16 bits
    return *(const uint32_t*)&h;
}
__device__ __forceinline__ float2 unpack_h2(uint32_t w) {
    return __half22float2(*(const __half2*)&w);
}

// A-side permuted layout over half2 words (p = k>>1). Tiles of 128 m x 32 p.
__device__ __forceinline__ size_t a16_idx(int m, int p) {
    const int mblk = m >> 7, kblk = p >> 5, r = m & 127, pq = p & 31;
    return (size_t)(mblk * 16 + kblk) * 4096 +
           ((r >> 4) << 9) + ((pq >> 3) << 7) + ((r & 7) << 4) +
           ((pq & 3) << 2) + (((pq >> 2) & 1) << 1) + ((r >> 3) & 1);
}
// B-side PAIR-PACKED layout: tiles of 64 n x 32 p.
__device__ __forceinline__ size_t b16_idx(int n, int p) {
    const int nblk = n >> 6, kblk = p >> 5, r = n & 63, pq = p & 31;
    const int nt = r >> 3;
    return (size_t)(nblk * 16 + kblk) * 2048 +
           ((nt >> 1) << 9) + ((pq >> 3) << 7) + ((r & 7) << 4) +
           ((pq & 3) << 2) + ((nt & 1) << 1) + ((pq >> 2) & 1);
}

// ---------------------------------------------------------------------------
// Pre-passes: fp16-round + fragment-permute into gmem
// ---------------------------------------------------------------------------
__global__ void __launch_bounds__(256) round_x(const float* __restrict__ x)
{
    const int n4 = BTC / 4;
    for (int f = blockIdx.x * 256 + threadIdx.x; f < n4; f += gridDim.x * 256) {
        const int m = f >> 8, c0 = (f & 255) << 2;
        const float4 v = ((const float4*)x)[f];
        const size_t base = a16_idx(m, c0 >> 1);
        g_x16[base]     = pack_h2(v.x, v.y);
        g_x16[base + 4] = pack_h2(v.z, v.w);
    }
}

__global__ void __launch_bounds__(256) round_w(const float* __restrict__ kw,
                                               const float* __restrict__ vw,
                                               const float* __restrict__ rw,
                                               const float* __restrict__ ow)
{
    const int z = blockIdx.y;
    const float* src = z == 0 ? kw : (z == 1 ? vw : (z == 2 ? rw : ow));
    uint32_t* dst    = z == 0 ? g_wk16 : (z == 1 ? g_wv16 : (z == 2 ? g_wr16 : g_wo16));
    const int n4 = WSZ / 4;
    for (int f = blockIdx.x * 256 + threadIdx.x; f < n4; f += gridDim.x * 256) {
        const int n = f >> 8, c0 = (f & 255) << 2;
        const float4 v = ((const float4*)src)[f];
        const size_t base = b16_idx(n, c0 >> 1);
        dst[base]     = pack_h2(v.x, v.y);
        dst[base + 4] = pack_h2(v.z, v.w);
    }
}

// ---------------------------------------------------------------------------
// FP16 mma.sync GEMM (m16n8k16), cp.async 2-stage pipeline, 3 CTAs/SM.
// Block tile 128(M) x 128(N) x 64(K), 128 threads.
// 4 warps in 2(M) x 2(N) grid -> warp tile 64x64.
// ---------------------------------------------------------------------------
#define STAGES 2
#define STGW 8192            // words per stage: 4096 A + 4096 B
#define STGB 32768           // bytes per stage
#define NKC 16               // 1024 / 64

template<bool ISOUT>
__global__ void __launch_bounds__(128, 3) gemm_mm(float* __restrict__ Yout)
{
    extern __shared__ __align__(16) uint32_t dsm[];   // STAGES*STGW words = 64 KB

    const int z = blockIdx.z;
    const uint32_t* A = ISOUT ? g_wkv16 : g_x16;
    const uint32_t* W = ISOUT ? g_wo16 : (z == 0 ? g_wk16 : (z == 1 ? g_wv16 : g_wr16));
    uint32_t* Y16     = ISOUT ? nullptr : (z == 0 ? g_k16 : (z == 1 ? g_v16 : g_r16));

    const int tid  = threadIdx.x;
    const int warp = tid >> 5, lane = tid & 31;
    const int mblk = blockIdx.y, nblk = blockIdx.x;   // 128-row, 128-col tiles
    const int wm   = warp & 1;          // 2 warps cover M (64 rows each)
    const int wn   = warp >> 1;         // 2 warps cover N (64 cols each)
    const int grp  = lane >> 2, qid = lane & 3;

    const uint32_t sbase = smem_u32(dsm);

    auto load_stage = [&](int slot, int kblk) {
        const uint32_t sb = sbase + slot * STGB;
        const uint32_t* at = A + (size_t)(mblk * 16 + kblk) * 4096;
#pragma unroll
        for (int i = 0; i < 8; i++) {               // 1024 A 16B-chunks
            const int ch = tid + (i << 7);
            cp16(sb + ch * 16, at + ch * 4);
        }
#pragma unroll
        for (int h = 0; h < 2; h++) {               // two 64-col B halves
            const uint32_t* bt = W + (size_t)((nblk * 2 + h) * 16 + kblk) * 2048;
#pragma unroll
            for (int i = 0; i < 4; i++) {           // 512 chunks per half
                const int ch = tid + (i << 7);
                cp16(sb + 16384 + h * 8192 + ch * 16, bt + ch * 4);
            }
        }
    };

    float acc[4][8][4];
#pragma unroll
    for (int a = 0; a < 4; a++)
#pragma unroll
        for (int b = 0; b < 8; b++)
#pragma unroll
            for (int c = 0; c < 4; c++) acc[a][b][c] = 0.f;

    load_stage(0, 0); cp_commit();

    for (int i = 0; i < NKC; i++) {
        cp_wait<0>();            // chunk i resident in slot i&1
        __syncthreads();         // everyone done with slot (i+1)&1 (chunk i-1)
        if (i + 1 < NKC) { load_stage((i + 1) & 1, i + 1); cp_commit(); }

        const uint32_t* stA = dsm + (i & 1) * STGW;                     // A tile
        const uint32_t* stB = dsm + (i & 1) * STGW + 4096 + (wn << 11); // B half
#pragma unroll
        for (int s = 0; s < 4; s++) {                     // 4 k16-steps per chunk
            uint4 af[4], bv[4];
#pragma unroll
            for (int mt = 0; mt < 4; mt++)
                af[mt] = *(const uint4*)&stA[(((wm << 2) + mt) << 9) + (s << 7) +
                                             (grp << 4) + (qid << 2)];
#pragma unroll
            for (int np = 0; np < 4; np++)
                bv[np] = *(const uint4*)&stB[(np << 9) + (s << 7) + (grp << 4) + (qid << 2)];
#pragma unroll
            for (int mt = 0; mt < 4; mt++)
#pragma unroll
                for (int np = 0; np < 4; np++) {
                    asm volatile(
                        "mma.sync.aligned.m16n8k16.row.col.f32.f16.f16.f32 "
                        "{%0,%1,%2,%3}, {%4,%5,%6,%7}, {%8,%9}, {%0,%1,%2,%3};"
                        : "+f"(acc[mt][2*np][0]), "+f"(acc[mt][2*np][1]),
                          "+f"(acc[mt][2*np][2]), "+f"(acc[mt][2*np][3])
                        : "r"(af[mt].x), "r"(af[mt].y), "r"(af[mt].z), "r"(af[mt].w),
                          "r"(bv[np].x), "r"(bv[np].y));
                    asm volatile(
                        "mma.sync.aligned.m16n8k16.row.col.f32.f16.f16.f32 "
                        "{%0,%1,%2,%3}, {%4,%5,%6,%7}, {%8,%9}, {%0,%1,%2,%3};"
                        : "+f"(acc[mt][2*np+1][0]), "+f"(acc[mt][2*np+1][1]),
                          "+f"(acc[mt][2*np+1][2]), "+f"(acc[mt][2*np+1][3])
                        : "r"(af[mt].x), "r"(af[mt].y), "r"(af[mt].z), "r"(af[mt].w),
                          "r"(bv[np].z), "r"(bv[np].w));
                }
        }
    }

    // --- epilogue ---
    const int m0 = mblk * 128 + wm * 64, n0 = nblk * 128 + wn * 64;
#pragma unroll
    for (int mt = 0; mt < 4; mt++)
#pragma unroll
        for (int nt = 0; nt < 8; nt++) {
            const int row = m0 + mt * 16 + grp;
            const int col = n0 + (nt << 3) + (qid << 1);   // even
            float o0 = acc[mt][nt][0], o1 = acc[mt][nt][1];
            float o2 = acc[mt][nt][2], o3 = acc[mt][nt][3];
            if (ISOUT) {
                *(float2*)(Yout + (size_t)row * CC + col)       = make_float2(o0, o1);
                *(float2*)(Yout + (size_t)(row + 8) * CC + col) = make_float2(o2, o3);
            } else {
                if (z == 2) {
                    o0 = 1.f / (1.f + __expf(-o0));
                    o1 = 1.f / (1.f + __expf(-o1));
                    o2 = 1.f / (1.f + __expf(-o2));
                    o3 = 1.f / (1.f + __expf(-o3));
                }
                Y16[(size_t)row * CP2 + (col >> 1)]       = pack_h2(o0, o1);
                Y16[(size_t)(row + 8) * CP2 + (col >> 1)] = pack_h2(o2, o3);
            }
        }
}

// ---------------------------------------------------------------------------
// WKV chunked parallel scan over packed half2 k/v/r.
// One thread per CHANNEL PAIR; NCH=128 chunks of 32 steps.
// ---------------------------------------------------------------------------
__global__ void __launch_bounds__(256) scan_states(const float* __restrict__ td)
{
    const int bid   = blockIdx.x;            // 1024 blocks = 4 b x 128 chunk x 2 pg
    const int b     = bid >> 8;
    const int chunk = (bid >> 1) & 127;
    const int pair  = ((bid & 1) << 8) + threadIdx.x;   // [0, 512)
    const int c0    = pair << 1;

    const float w0 = expf(td[c0]), w1 = expf(td[c0 + 1]);
    const size_t base = (size_t)(b * TT + chunk * CLEN) * CP2 + pair;

    float aa0 = 0.f, bb0 = 0.f, pp0 = -1e38f;
    float aa1 = 0.f, bb1 = 0.f, pp1 = -1e38f;
#pragma unroll 4
    for (int t = 0; t < CLEN; t++) {
        const float2 kt = unpack_h2(g_k16[base + (size_t)t * CP2]);
        const float2 vt = unpack_h2(g_v16[base + (size_t)t * CP2]);
        {
            const float ww2 = pp0 - w0;
            const float p2  = fmaxf(ww2, kt.x);
            const float e1b = __expf(ww2 - p2);
            const float e2b = __expf(kt.x - p2);
            aa0 = e1b * aa0 + e2b * vt.x;
            bb0 = e1b * bb0 + e2b;
            pp0 = p2;
        }
        {
            const float ww2 = pp1 - w1;
            const float p2  = fmaxf(ww2, kt.y);
            const float e1b = __expf(ww2 - p2);
            const float e2b = __expf(kt.y - p2);
            aa1 = e1b * aa1 + e2b * vt.y;
            bb1 = e1b * bb1 + e2b;
            pp1 = p2;
        }
    }
    const int i = b * CC + c0;
    *(float2*)&g_saa[chunk][i] = make_float2(aa0, aa1);
    *(float2*)&g_sbb[chunk][i] = make_float2(bb0, bb1);
    *(float2*)&g_spp[chunk][i] = make_float2(pp0, pp1);
}

__global__ void __launch_bounds__(256) scan_combine(const float* __restrict__ td,
                                                    const float* __restrict__ aa0,
                                                    const float* __restrict__ bb0,
                                                    const float* __restrict__ pp0)
{
    const int i = blockIdx.x * 256 + threadIdx.x;   // [0, 4096)
    const int c = i & (CC - 1);
    const float w   = expf(td[c]);
    const float dec = (float)CLEN * w;

    float aa = aa0[i], bb = bb0[i], pp = pp0[i];
#pragma unroll 8
    for (int ch = 0; ch < NCH; ch++) {
        g_iaa[ch][i] = aa; g_ibb[ch][i] = bb; g_ipp[ch][i] = pp;
        const float ppd = pp - dec;
        const float aL = g_saa[ch][i], bL = g_sbb[ch][i], pL = g_spp[ch][i];
        const float p  = fmaxf(ppd, pL);
        const float e1 = __expf(ppd - p);
        const float e2 = __expf(pL - p);
        aa = e1 * aa + e2 * aL;
        bb = e1 * bb + e2 * bL;
        pp = p;
    }
}

__global__ void __launch_bounds__(256) scan_out(const float* __restrict__ td,
                                                const float* __restrict__ tf,
                                                float* __restrict__ out_tail)
{
    const int bid   = blockIdx.x;            // 1024 blocks
    const int b     = bid >> 8;
    const int chunk = (bid >> 1) & 127;
    const int pair  = ((bid & 1) << 8) + threadIdx.x;   // [0, 512)
    const int c0    = pair << 1;
    const int i     = b * CC + c0;

    const float w0 = expf(td[c0]), w1 = expf(td[c0 + 1]);
    const float u0 = tf[c0],       u1 = tf[c0 + 1];
    float2 aa = *(const float2*)&g_iaa[chunk][i];
    float2 bb = *(const float2*)&g_ibb[chunk][i];
    float2 pp = *(const float2*)&g_ipp[chunk][i];

    const size_t base = (size_t)(b * TT + chunk * CLEN) * CP2 + pair;
    const int mbase = b * TT + chunk * CLEN;

    // strength-reduced a16_idx: chunk (32 steps) never crosses an mblk
    // boundary, and the pair-dependent K-part is constant.
    const int pq = pair & 31, kblk = pair >> 5;
    const size_t tile0 = (size_t)((mbase >> 7) * 16 + kblk) * 4096 +
                         ((pq >> 3) << 7) + ((pq & 3) << 2) + (((pq >> 2) & 1) << 1);
    const int r0 = mbase & 127;

#pragma unroll 4
    for (int t = 0; t < CLEN; t++) {
        const float2 kt = unpack_h2(g_k16[base + (size_t)t * CP2]);
        const float2 vt = unpack_h2(g_v16[base + (size_t)t * CP2]);
        const float2 rt = unpack_h2(g_r16[base + (size_t)t * CP2]);
        float wkv0, wkv1;
        {
            const float ww = u0 + kt.x;
            const float p  = fmaxf(pp.x, ww);
            const float e1 = __expf(pp.x - p);
            const float e2 = __expf(ww - p);
            wkv0 = __fdividef(e1 * aa.x + e2 * vt.x, e1 * bb.x + e2);
            const float ww2 = pp.x - w0;
            const float p2  = fmaxf(ww2, kt.x);
            const float e1b = __expf(ww2 - p2);
            const float e2b = __expf(kt.x - p2);
            aa.x = e1b * aa.x + e2b * vt.x;
            bb.x = e1b * bb.x + e2b;
            pp.x = p2;
        }
        {
            const float ww = u1 + kt.y;
            const float p  = fmaxf(pp.y, ww);
            const float e1 = __expf(pp.y - p);
            const float e2 = __expf(ww - p);
            wkv1 = __fdividef(e1 * aa.y + e2 * vt.y, e1 * bb.y + e2);
            const float ww2 = pp.y - w1;
            const float p2  = fmaxf(ww2, kt.y);
            const float e1b = __expf(ww2 - p2);
            const float e2b = __expf(kt.y - p2);
            aa.y = e1b * aa.y + e2b * vt.y;
            bb.y = e1b * bb.y + e2b;
            pp.y = p2;
        }
        const int r = r0 + t;
        g_wkv16[tile0 + ((r >> 4) << 9) + ((r & 7) << 4) + ((r >> 3) & 1)] =
            pack_h2(rt.x * wkv0, rt.y * wkv1);
    }

    if (chunk == NCH - 1) {
        *(float2*)(out_tail + i)           = aa;
        *(float2*)(out_tail + NBC + i)     = bb;
        *(float2*)(out_tail + 2 * NBC + i) = pp;
    }
}

// ---------------------------------------------------------------------------
// Launch
// ---------------------------------------------------------------------------
extern "C" void kernel_launch(void* const* d_in, const int* in_sizes, int n_in,
                              void* d_out, int out_size)
{
    const float* x    = (const float*)d_in[0];
    const float* kw   = (const float*)d_in[1];
    const float* vw   = (const float*)d_in[2];
    const float* rw   = (const float*)d_in[3];
    const float* ow   = (const float*)d_in[4];
    const float* td   = (const float*)d_in[5];
    const float* tf   = (const float*)d_in[6];
    const float* aa0  = (const float*)d_in[7];
    const float* bb0  = (const float*)d_in[8];
    const float* pp0  = (const float*)d_in[9];

    float* out  = (float*)d_out;
    float* tail = out + (size_t)BTC;

    static bool configured = false;
    if (!configured) {
        cudaFuncSetAttribute(gemm_mm<false>, cudaFuncAttributeMaxDynamicSharedMemorySize,
                             STAGES * STGB);
        cudaFuncSetAttribute(gemm_mm<true>,  cudaFuncAttributeMaxDynamicSharedMemorySize,
                             STAGES * STGB);
        configured = true;
    }

    // pre-round to fp16 + fragment-permute into gmem
    round_x<<<2048, 256>>>(x);
    round_w<<<dim3(64, 4), 256>>>(kw, vw, rw, ow);

    // fused k/v/r projections (fp16 packed outputs)
    gemm_mm<false><<<dim3(8, 128, 3), 128, STAGES * STGB>>>(nullptr);

    // chunked parallel WKV scan (channel-pair threads, 128 chunks)
    scan_states<<<1024, 256>>>(td);
    scan_combine<<<16, 256>>>(td, aa0, bb0, pp0);
    scan_out<<<1024, 256>>>(td, tf, tail);

    // out = (r * wkv) @ ow^T  (A pre-multiplied, packed, permuted by scan_out)
    gemm_mm<true><<<dim3(8, 128, 1), 128, STAGES * STGB>>>(out);
}

// round 15
// speedup vs baseline: 1.0418x; 1.0418x over previous
#include <cuda_runtime.h>
#include <cuda_fp16.h>
#include <cstdint>
#include <cstddef>

// Problem sizes (fixed)
#define BB 4
#define TT 4096
#define CC 1024
#define MM (BB * TT)          // 16384
#define BTC (BB * TT * CC)    // 16,777,216
#define NCH 64                // scan chunks along T
#define CLEN (TT / NCH)       // 64
#define NBC (BB * CC)         // 4096
#define WSZ (CC * CC)         // 1,048,576
#define CP2 (CC / 2)          // 512 channel pairs

// ---------------------------------------------------------------------------
// Scratch in device globals (no cudaMalloc allowed).
// ---------------------------------------------------------------------------
__device__ __align__(16) uint32_t g_k16[BTC / 2];
__device__ __align__(16) uint32_t g_v16[BTC / 2];
__device__ __align__(16) uint32_t g_r16[BTC / 2];
__device__ __align__(16) uint32_t g_x16[BTC / 2];     // permuted fp16 x
__device__ __align__(16) uint32_t g_wkv16[BTC / 2];   // permuted fp16 (r*wkv)
__device__ __align__(16) uint32_t g_wk16[WSZ / 2], g_wv16[WSZ / 2],
                                  g_wr16[WSZ / 2], g_wo16[WSZ / 2];
__device__ float g_saa[NCH][NBC], g_sbb[NCH][NBC], g_spp[NCH][NBC];
__device__ float g_iaa[NCH][NBC], g_ibb[NCH][NBC], g_ipp[NCH][NBC];

// ---------------------------------------------------------------------------
// Helpers
// ---------------------------------------------------------------------------
__device__ __forceinline__ uint32_t smem_u32(const void* p) {
    return (uint32_t)__cvta_generic_to_shared(p);
}
__device__ __forceinline__ void cp16(uint32_t smem_dst, const void* gmem_src) {
    asm volatile("cp.async.cg.shared.global [%0], [%1], 16;\n" :: "r"(smem_dst), "l"(gmem_src));
}
__device__ __forceinline__ void cp_commit() { asm volatile("cp.async.commit_group;\n"); }
template<int N>
__device__ __forceinline__ void cp_wait() { asm volatile("cp.async.wait_group %0;\n" :: "n"(N)); }

__device__ __forceinline__ uint32_t pack_h2(float lo, float hi) {
    const __half2 h = __floats2half2_rn(lo, hi);   // lo -> low 16 bits
    return *(const uint32_t*)&h;
}
__device__ __forceinline__ float2 unpack_h2(uint32_t w) {
    return __half22float2(*(const __half2*)&w);
}

// A-side permuted layout over half2 words (p = k>>1). Tiles of 128 m x 32 p.
__device__ __forceinline__ size_t a16_idx(int m, int p) {
    const int mblk = m >> 7, kblk = p >> 5, r = m & 127, pq = p & 31;
    return (size_t)(mblk * 16 + kblk) * 4096 +
           ((r >> 4) << 9) + ((pq >> 3) << 7) + ((r & 7) << 4) +
           ((pq & 3) << 2) + (((pq >> 2) & 1) << 1) + ((r >> 3) & 1);
}
// B-side PAIR-PACKED layout: tiles of 64 n x 32 p.
__device__ __forceinline__ size_t b16_idx(int n, int p) {
    const int nblk = n >> 6, kblk = p >> 5, r = n & 63, pq = p & 31;
    const int nt = r >> 3;
    return (size_t)(nblk * 16 + kblk) * 2048 +
           ((nt >> 1) << 9) + ((pq >> 3) << 7) + ((r & 7) << 4) +
           ((pq & 3) << 2) + ((nt & 1) << 1) + ((pq >> 2) & 1);
}

// ---------------------------------------------------------------------------
// Fused pre-pass: fp16-round + fragment-permute x and all 4 weights.
// Blocks [0,1024) handle x; blocks [1024,1536) handle weights (128 per weight).
// ---------------------------------------------------------------------------
__global__ void __launch_bounds__(256) round_all(const float* __restrict__ x,
                                                 const float* __restrict__ kw,
                                                 const float* __restrict__ vw,
                                                 const float* __restrict__ rw,
                                                 const float* __restrict__ ow)
{
    const int bx = blockIdx.x;
    if (bx < 1024) {
        const int n4 = BTC / 4;
        for (int f = bx * 256 + threadIdx.x; f < n4; f += 1024 * 256) {
            const int m = f >> 8, c0 = (f & 255) << 2;
            const float4 v = ((const float4*)x)[f];
            const size_t base = a16_idx(m, c0 >> 1);
            g_x16[base]     = pack_h2(v.x, v.y);
            g_x16[base + 4] = pack_h2(v.z, v.w);
        }
    } else {
        const int wb = bx - 1024;            // [0, 512)
        const int z  = wb >> 7;              // 128 blocks per weight
        const float* src = z == 0 ? kw : (z == 1 ? vw : (z == 2 ? rw : ow));
        uint32_t* dst    = z == 0 ? g_wk16 : (z == 1 ? g_wv16 : (z == 2 ? g_wr16 : g_wo16));
        const int n4 = WSZ / 4;
        for (int f = (wb & 127) * 256 + threadIdx.x; f < n4; f += 128 * 256) {
            const int n = f >> 8, c0 = (f & 255) << 2;
            const float4 v = ((const float4*)src)[f];
            const size_t base = b16_idx(n, c0 >> 1);
            dst[base]     = pack_h2(v.x, v.y);
            dst[base + 4] = pack_h2(v.z, v.w);
        }
    }
}

// ---------------------------------------------------------------------------
// FP16 mma.sync GEMM (m16n8k16), cp.async 2-stage pipeline, 3 CTAs/SM.
// Block tile 128(M) x 128(N) x 64(K), 128 threads.
// 4 warps in 2(M) x 2(N) grid -> warp tile 64x64.
// ---------------------------------------------------------------------------
#define STAGES 2
#define STGW 8192            // words per stage: 4096 A + 4096 B
#define STGB 32768           // bytes per stage
#define NKC 16               // 1024 / 64

template<bool ISOUT>
__global__ void __launch_bounds__(128, 3) gemm_mm(float* __restrict__ Yout)
{
    extern __shared__ __align__(16) uint32_t dsm[];   // STAGES*STGW words = 64 KB

    const int z = blockIdx.z;
    const uint32_t* A = ISOUT ? g_wkv16 : g_x16;
    const uint32_t* W = ISOUT ? g_wo16 : (z == 0 ? g_wk16 : (z == 1 ? g_wv16 : g_wr16));
    uint32_t* Y16     = ISOUT ? nullptr : (z == 0 ? g_k16 : (z == 1 ? g_v16 : g_r16));

    const int tid  = threadIdx.x;
    const int warp = tid >> 5, lane = tid & 31;
    const int mblk = blockIdx.y, nblk = blockIdx.x;   // 128-row, 128-col tiles
    const int wm   = warp & 1;          // 2 warps cover M (64 rows each)
    const int wn   = warp >> 1;         // 2 warps cover N (64 cols each)
    const int grp  = lane >> 2, qid = lane & 3;

    const uint32_t sbase = smem_u32(dsm);

    auto load_stage = [&](int slot, int kblk) {
        const uint32_t sb = sbase + slot * STGB;
        const uint32_t* at = A + (size_t)(mblk * 16 + kblk) * 4096;
#pragma unroll
        for (int i = 0; i < 8; i++) {               // 1024 A 16B-chunks
            const int ch = tid + (i << 7);
            cp16(sb + ch * 16, at + ch * 4);
        }
#pragma unroll
        for (int h = 0; h < 2; h++) {               // two 64-col B halves
            const uint32_t* bt = W + (size_t)((nblk * 2 + h) * 16 + kblk) * 2048;
#pragma unroll
            for (int i = 0; i < 4; i++) {           // 512 chunks per half
                const int ch = tid + (i << 7);
                cp16(sb + 16384 + h * 8192 + ch * 16, bt + ch * 4);
            }
        }
    };

    float acc[4][8][4];
#pragma unroll
    for (int a = 0; a < 4; a++)
#pragma unroll
        for (int b = 0; b < 8; b++)
#pragma unroll
            for (int c = 0; c < 4; c++) acc[a][b][c] = 0.f;

    load_stage(0, 0); cp_commit();

    for (int i = 0; i < NKC; i++) {
        cp_wait<0>();            // chunk i resident in slot i&1
        __syncthreads();         // everyone done with slot (i+1)&1 (chunk i-1)
        if (i + 1 < NKC) { load_stage((i + 1) & 1, i + 1); cp_commit(); }

        const uint32_t* stA = dsm + (i & 1) * STGW;                     // A tile
        const uint32_t* stB = dsm + (i & 1) * STGW + 4096 + (wn << 11); // B half
#pragma unroll
        for (int s = 0; s < 4; s++) {                     // 4 k16-steps per chunk
            uint4 af[4], bv[4];
#pragma unroll
            for (int mt = 0; mt < 4; mt++)
                af[mt] = *(const uint4*)&stA[(((wm << 2) + mt) << 9) + (s << 7) +
                                             (grp << 4) + (qid << 2)];
#pragma unroll
            for (int np = 0; np < 4; np++)
                bv[np] = *(const uint4*)&stB[(np << 9) + (s << 7) + (grp << 4) + (qid << 2)];
#pragma unroll
            for (int mt = 0; mt < 4; mt++)
#pragma unroll
                for (int np = 0; np < 4; np++) {
                    asm volatile(
                        "mma.sync.aligned.m16n8k16.row.col.f32.f16.f16.f32 "
                        "{%0,%1,%2,%3}, {%4,%5,%6,%7}, {%8,%9}, {%0,%1,%2,%3};"
                        : "+f"(acc[mt][2*np][0]), "+f"(acc[mt][2*np][1]),
                          "+f"(acc[mt][2*np][2]), "+f"(acc[mt][2*np][3])
                        : "r"(af[mt].x), "r"(af[mt].y), "r"(af[mt].z), "r"(af[mt].w),
                          "r"(bv[np].x), "r"(bv[np].y));
                    asm volatile(
                        "mma.sync.aligned.m16n8k16.row.col.f32.f16.f16.f32 "
                        "{%0,%1,%2,%3}, {%4,%5,%6,%7}, {%8,%9}, {%0,%1,%2,%3};"
                        : "+f"(acc[mt][2*np+1][0]), "+f"(acc[mt][2*np+1][1]),
                          "+f"(acc[mt][2*np+1][2]), "+f"(acc[mt][2*np+1][3])
                        : "r"(af[mt].x), "r"(af[mt].y), "r"(af[mt].z), "r"(af[mt].w),
                          "r"(bv[np].z), "r"(bv[np].w));
                }
        }
    }

    // --- epilogue ---
    const int m0 = mblk * 128 + wm * 64, n0 = nblk * 128 + wn * 64;
#pragma unroll
    for (int mt = 0; mt < 4; mt++)
#pragma unroll
        for (int nt = 0; nt < 8; nt++) {
            const int row = m0 + mt * 16 + grp;
            const int col = n0 + (nt << 3) + (qid << 1);   // even
            float o0 = acc[mt][nt][0], o1 = acc[mt][nt][1];
            float o2 = acc[mt][nt][2], o3 = acc[mt][nt][3];
            if (ISOUT) {
                *(float2*)(Yout + (size_t)row * CC + col)       = make_float2(o0, o1);
                *(float2*)(Yout + (size_t)(row + 8) * CC + col) = make_float2(o2, o3);
            } else {
                if (z == 2) {
                    o0 = 1.f / (1.f + __expf(-o0));
                    o1 = 1.f / (1.f + __expf(-o1));
                    o2 = 1.f / (1.f + __expf(-o2));
                    o3 = 1.f / (1.f + __expf(-o3));
                }
                Y16[(size_t)row * CP2 + (col >> 1)]       = pack_h2(o0, o1);
                Y16[(size_t)(row + 8) * CP2 + (col >> 1)] = pack_h2(o2, o3);
            }
        }
}

// ---------------------------------------------------------------------------
// WKV chunked parallel scan over packed half2 k/v/r.
// One thread per CHANNEL PAIR; NCH=64 chunks of 64 steps.
// ---------------------------------------------------------------------------
__global__ void __launch_bounds__(256) scan_states(const float* __restrict__ td)
{
    const int bid   = blockIdx.x;            // 512 blocks = 4 b x 64 chunk x 2 pg
    const int b     = bid >> 7;
    const int chunk = (bid >> 1) & 63;
    const int pair  = ((bid & 1) << 8) + threadIdx.x;   // [0, 512)
    const int c0    = pair << 1;

    const float w0 = expf(td[c0]), w1 = expf(td[c0 + 1]);
    const size_t base = (size_t)(b * TT + chunk * CLEN) * CP2 + pair;

    float aa0 = 0.f, bb0 = 0.f, pp0 = -1e38f;
    float aa1 = 0.f, bb1 = 0.f, pp1 = -1e38f;
#pragma unroll 4
    for (int t = 0; t < CLEN; t++) {
        const float2 kt = unpack_h2(g_k16[base + (size_t)t * CP2]);
        const float2 vt = unpack_h2(g_v16[base + (size_t)t * CP2]);
        {
            const float ww2 = pp0 - w0;
            const float p2  = fmaxf(ww2, kt.x);
            const float e1b = __expf(ww2 - p2);
            const float e2b = __expf(kt.x - p2);
            aa0 = e1b * aa0 + e2b * vt.x;
            bb0 = e1b * bb0 + e2b;
            pp0 = p2;
        }
        {
            const float ww2 = pp1 - w1;
            const float p2  = fmaxf(ww2, kt.y);
            const float e1b = __expf(ww2 - p2);
            const float e2b = __expf(kt.y - p2);
            aa1 = e1b * aa1 + e2b * vt.y;
            bb1 = e1b * bb1 + e2b;
            pp1 = p2;
        }
    }
    const int i = b * CC + c0;
    *(float2*)&g_saa[chunk][i] = make_float2(aa0, aa1);
    *(float2*)&g_sbb[chunk][i] = make_float2(bb0, bb1);
    *(float2*)&g_spp[chunk][i] = make_float2(pp0, pp1);
}

__global__ void __launch_bounds__(256) scan_combine(const float* __restrict__ td,
                                                    const float* __restrict__ aa0,
                                                    const float* __restrict__ bb0,
                                                    const float* __restrict__ pp0)
{
    const int i = blockIdx.x * 256 + threadIdx.x;   // [0, 4096)
    const int c = i & (CC - 1);
    const float w   = expf(td[c]);
    const float dec = (float)CLEN * w;

    float aa = aa0[i], bb = bb0[i], pp = pp0[i];
#pragma unroll 8
    for (int ch = 0; ch < NCH; ch++) {
        g_iaa[ch][i] = aa; g_ibb[ch][i] = bb; g_ipp[ch][i] = pp;
        const float ppd = pp - dec;
        const float aL = g_saa[ch][i], bL = g_sbb[ch][i], pL = g_spp[ch][i];
        const float p  = fmaxf(ppd, pL);
        const float e1 = __expf(ppd - p);
        const float e2 = __expf(pL - p);
        aa = e1 * aa + e2 * aL;
        bb = e1 * bb + e2 * bL;
        pp = p;
    }
}

__global__ void __launch_bounds__(256) scan_out(const float* __restrict__ td,
                                                const float* __restrict__ tf,
                                                float* __restrict__ out_tail)
{
    const int bid   = blockIdx.x;            // 512 blocks
    const int b     = bid >> 7;
    const int chunk = (bid >> 1) & 63;
    const int pair  = ((bid & 1) << 8) + threadIdx.x;   // [0, 512)
    const int c0    = pair << 1;
    const int i     = b * CC + c0;

    const float w0 = expf(td[c0]), w1 = expf(td[c0 + 1]);
    const float u0 = tf[c0],       u1 = tf[c0 + 1];
    float2 aa = *(const float2*)&g_iaa[chunk][i];
    float2 bb = *(const float2*)&g_ibb[chunk][i];
    float2 pp = *(const float2*)&g_ipp[chunk][i];

    const size_t base = (size_t)(b * TT + chunk * CLEN) * CP2 + pair;
    const int mbase = b * TT + chunk * CLEN;

    // strength-reduced a16_idx: a 64-step chunk never crosses an mblk
    // boundary (mbase % 64 == 0), and the pair-dependent K-part is constant.
    const int pq = pair & 31, kblk = pair >> 5;
    const size_t tile0 = (size_t)((mbase >> 7) * 16 + kblk) * 4096 +
                         ((pq >> 3) << 7) + ((pq & 3) << 2) + (((pq >> 2) & 1) << 1);
    const int r0 = mbase & 127;

#pragma unroll 4
    for (int t = 0; t < CLEN; t++) {
        const float2 kt = unpack_h2(g_k16[base + (size_t)t * CP2]);
        const float2 vt = unpack_h2(g_v16[base + (size_t)t * CP2]);
        const float2 rt = unpack_h2(g_r16[base + (size_t)t * CP2]);
        float wkv0, wkv1;
        {
            const float ww = u0 + kt.x;
            const float p  = fmaxf(pp.x, ww);
            const float e1 = __expf(pp.x - p);
            const float e2 = __expf(ww - p);
            wkv0 = __fdividef(e1 * aa.x + e2 * vt.x, e1 * bb.x + e2);
            const float ww2 = pp.x - w0;
            const float p2  = fmaxf(ww2, kt.x);
            const float e1b = __expf(ww2 - p2);
            const float e2b = __expf(kt.x - p2);
            aa.x = e1b * aa.x + e2b * vt.x;
            bb.x = e1b * bb.x + e2b;
            pp.x = p2;
        }
        {
            const float ww = u1 + kt.y;
            const float p  = fmaxf(pp.y, ww);
            const float e1 = __expf(pp.y - p);
            const float e2 = __expf(ww - p);
            wkv1 = __fdividef(e1 * aa.y + e2 * vt.y, e1 * bb.y + e2);
            const float ww2 = pp.y - w1;
            const float p2  = fmaxf(ww2, kt.y);
            const float e1b = __expf(ww2 - p2);
            const float e2b = __expf(kt.y - p2);
            aa.y = e1b * aa.y + e2b * vt.y;
            bb.y = e1b * bb.y + e2b;
            pp.y = p2;
        }
        const int r = r0 + t;
        g_wkv16[tile0 + ((r >> 4) << 9) + ((r & 7) << 4) + ((r >> 3) & 1)] =
            pack_h2(rt.x * wkv0, rt.y * wkv1);
    }

    if (chunk == NCH - 1) {
        *(float2*)(out_tail + i)           = aa;
        *(float2*)(out_tail + NBC + i)     = bb;
        *(float2*)(out_tail + 2 * NBC + i) = pp;
    }
}

// ---------------------------------------------------------------------------
// Launch
// ---------------------------------------------------------------------------
extern "C" void kernel_launch(void* const* d_in, const int* in_sizes, int n_in,
                              void* d_out, int out_size)
{
    const float* x    = (const float*)d_in[0];
    const float* kw   = (const float*)d_in[1];
    const float* vw   = (const float*)d_in[2];
    const float* rw   = (const float*)d_in[3];
    const float* ow   = (const float*)d_in[4];
    const float* td   = (const float*)d_in[5];
    const float* tf   = (const float*)d_in[6];
    const float* aa0  = (const float*)d_in[7];
    const float* bb0  = (const float*)d_in[8];
    const float* pp0  = (const float*)d_in[9];

    float* out  = (float*)d_out;
    float* tail = out + (size_t)BTC;

    static bool configured = false;
    if (!configured) {
        cudaFuncSetAttribute(gemm_mm<false>, cudaFuncAttributeMaxDynamicSharedMemorySize,
                             STAGES * STGB);
        cudaFuncSetAttribute(gemm_mm<true>,  cudaFuncAttributeMaxDynamicSharedMemorySize,
                             STAGES * STGB);
        configured = true;
    }

    // fused pre-pass: fp16-round + fragment-permute x and weights
    round_all<<<1536, 256>>>(x, kw, vw, rw, ow);

    // fused k/v/r projections (fp16 packed outputs)
    gemm_mm<false><<<dim3(8, 128, 3), 128, STAGES * STGB>>>(nullptr);

    // chunked parallel WKV scan (channel-pair threads, 64 chunks)
    scan_states<<<512, 256>>>(td);
    scan_combine<<<16, 256>>>(td, aa0, bb0, pp0);
    scan_out<<<512, 256>>>(td, tf, tail);

    // out = (r * wkv) @ ow^T  (A pre-multiplied, packed, permuted by scan_out)
    gemm_mm<true><<<dim3(8, 128, 1), 128, STAGES * STGB>>>(out);
}

// round 16
// speedup vs baseline: 1.0830x; 1.0395x over previous
#include <cuda_runtime.h>
#include <cuda_fp16.h>
#include <cstdint>
#include <cstddef>

// Problem sizes (fixed)
#define BB 4
#define TT 4096
#define CC 1024
#define MM (BB * TT)          // 16384
#define BTC (BB * TT * CC)    // 16,777,216
#define NCH 64                // scan chunks along T
#define CLEN (TT / NCH)       // 64
#define NBC (BB * CC)         // 4096
#define WSZ (CC * CC)         // 1,048,576
#define CP2 (CC / 2)          // 512 channel pairs

// ---------------------------------------------------------------------------
// Scratch in device globals (no cudaMalloc allowed).
// ---------------------------------------------------------------------------
__device__ __align__(16) uint32_t g_k16[BTC / 2];
__device__ __align__(16) uint32_t g_v16[BTC / 2];
__device__ __align__(16) uint32_t g_r16[BTC / 2];
__device__ __align__(16) uint32_t g_x16[BTC / 2];     // permuted fp16 x
__device__ __align__(16) uint32_t g_wkv16[BTC / 2];   // permuted fp16 (r*wkv)
__device__ __align__(16) uint32_t g_wk16[WSZ / 2], g_wv16[WSZ / 2],
                                  g_wr16[WSZ / 2], g_wo16[WSZ / 2];
__device__ float g_saa[NCH][NBC], g_sbb[NCH][NBC], g_spp[NCH][NBC];
__device__ float g_iaa[NCH][NBC], g_ibb[NCH][NBC], g_ipp[NCH][NBC];

// ---------------------------------------------------------------------------
// Helpers
// ---------------------------------------------------------------------------
__device__ __forceinline__ uint32_t smem_u32(const void* p) {
    return (uint32_t)__cvta_generic_to_shared(p);
}
__device__ __forceinline__ void cp16(uint32_t smem_dst, const void* gmem_src) {
    asm volatile("cp.async.cg.shared.global [%0], [%1], 16;\n" :: "r"(smem_dst), "l"(gmem_src));
}
__device__ __forceinline__ void cp_commit() { asm volatile("cp.async.commit_group;\n"); }
template<int N>
__device__ __forceinline__ void cp_wait() { asm volatile("cp.async.wait_group %0;\n" :: "n"(N)); }

__device__ __forceinline__ uint32_t pack_h2(float lo, float hi) {
    const __half2 h = __floats2half2_rn(lo, hi);   // lo -> low 16 bits
    return *(const uint32_t*)&h;
}
__device__ __forceinline__ float2 unpack_h2(uint32_t w) {
    return __half22float2(*(const __half2*)&w);
}

// A-side permuted layout over half2 words (p = k>>1). Tiles of 128 m x 32 p.
__device__ __forceinline__ size_t a16_idx(int m, int p) {
    const int mblk = m >> 7, kblk = p >> 5, r = m & 127, pq = p & 31;
    return (size_t)(mblk * 16 + kblk) * 4096 +
           ((r >> 4) << 9) + ((pq >> 3) << 7) + ((r & 7) << 4) +
           ((pq & 3) << 2) + (((pq >> 2) & 1) << 1) + ((r >> 3) & 1);
}
// B-side PAIR-PACKED layout: tiles of 64 n x 32 p.
__device__ __forceinline__ size_t b16_idx(int n, int p) {
    const int nblk = n >> 6, kblk = p >> 5, r = n & 63, pq = p & 31;
    const int nt = r >> 3;
    return (size_t)(nblk * 16 + kblk) * 2048 +
           ((nt >> 1) << 9) + ((pq >> 3) << 7) + ((r & 7) << 4) +
           ((pq & 3) << 2) + ((nt & 1) << 1) + ((pq >> 2) & 1);
}

// ---------------------------------------------------------------------------
// Fused pre-pass: fp16-round + fragment-permute x and all 4 weights.
// Blocks [0,1024) handle x; blocks [1024,1536) handle weights (128 per weight).
// ---------------------------------------------------------------------------
__global__ void __launch_bounds__(256) round_all(const float* __restrict__ x,
                                                 const float* __restrict__ kw,
                                                 const float* __restrict__ vw,
                                                 const float* __restrict__ rw,
                                                 const float* __restrict__ ow)
{
    const int bx = blockIdx.x;
    if (bx < 1024) {
        const int n4 = BTC / 4;
        for (int f = bx * 256 + threadIdx.x; f < n4; f += 1024 * 256) {
            const int m = f >> 8, c0 = (f & 255) << 2;
            const float4 v = ((const float4*)x)[f];
            const size_t base = a16_idx(m, c0 >> 1);
            g_x16[base]     = pack_h2(v.x, v.y);
            g_x16[base + 4] = pack_h2(v.z, v.w);
        }
    } else {
        const int wb = bx - 1024;            // [0, 512)
        const int z  = wb >> 7;              // 128 blocks per weight
        const float* src = z == 0 ? kw : (z == 1 ? vw : (z == 2 ? rw : ow));
        uint32_t* dst    = z == 0 ? g_wk16 : (z == 1 ? g_wv16 : (z == 2 ? g_wr16 : g_wo16));
        const int n4 = WSZ / 4;
        for (int f = (wb & 127) * 256 + threadIdx.x; f < n4; f += 128 * 256) {
            const int n = f >> 8, c0 = (f & 255) << 2;
            const float4 v = ((const float4*)src)[f];
            const size_t base = b16_idx(n, c0 >> 1);
            dst[base]     = pack_h2(v.x, v.y);
            dst[base + 4] = pack_h2(v.z, v.w);
        }
    }
}

// ---------------------------------------------------------------------------
// FP16 mma.sync GEMM (m16n8k16), cp.async 2-stage pipeline, 3 CTAs/SM.
// Block tile 128(M) x 128(N) x 64(K), 128 threads.
// 4 warps in 2(M) x 2(N) grid -> warp tile 64x64.
// ---------------------------------------------------------------------------
#define STAGES 2
#define STGW 8192            // words per stage: 4096 A + 4096 B
#define STGB 32768           // bytes per stage
#define NKC 16               // 1024 / 64

template<bool ISOUT>
__global__ void __launch_bounds__(128, 3) gemm_mm(float* __restrict__ Yout)
{
    extern __shared__ __align__(16) uint32_t dsm[];   // STAGES*STGW words = 64 KB

    const int z = blockIdx.z;
    const uint32_t* A = ISOUT ? g_wkv16 : g_x16;
    const uint32_t* W = ISOUT ? g_wo16 : (z == 0 ? g_wk16 : (z == 1 ? g_wv16 : g_wr16));
    uint32_t* Y16     = ISOUT ? nullptr : (z == 0 ? g_k16 : (z == 1 ? g_v16 : g_r16));

    const int tid  = threadIdx.x;
    const int warp = tid >> 5, lane = tid & 31;
    const int mblk = blockIdx.y, nblk = blockIdx.x;   // 128-row, 128-col tiles
    const int wm   = warp & 1;          // 2 warps cover M (64 rows each)
    const int wn   = warp >> 1;         // 2 warps cover N (64 cols each)
    const int grp  = lane >> 2, qid = lane & 3;

    const uint32_t sbase = smem_u32(dsm);

    auto load_stage = [&](int slot, int kblk) {
        const uint32_t sb = sbase + slot * STGB;
        const uint32_t* at = A + (size_t)(mblk * 16 + kblk) * 4096;
#pragma unroll
        for (int i = 0; i < 8; i++) {               // 1024 A 16B-chunks
            const int ch = tid + (i << 7);
            cp16(sb + ch * 16, at + ch * 4);
        }
#pragma unroll
        for (int h = 0; h < 2; h++) {               // two 64-col B halves
            const uint32_t* bt = W + (size_t)((nblk * 2 + h) * 16 + kblk) * 2048;
#pragma unroll
            for (int i = 0; i < 4; i++) {           // 512 chunks per half
                const int ch = tid + (i << 7);
                cp16(sb + 16384 + h * 8192 + ch * 16, bt + ch * 4);
            }
        }
    };

    float acc[4][8][4];
#pragma unroll
    for (int a = 0; a < 4; a++)
#pragma unroll
        for (int b = 0; b < 8; b++)
#pragma unroll
            for (int c = 0; c < 4; c++) acc[a][b][c] = 0.f;

    load_stage(0, 0); cp_commit();

    for (int i = 0; i < NKC; i++) {
        cp_wait<0>();            // chunk i resident in slot i&1
        __syncthreads();         // everyone done with slot (i+1)&1 (chunk i-1)
        if (i + 1 < NKC) { load_stage((i + 1) & 1, i + 1); cp_commit(); }

        const uint32_t* stA = dsm + (i & 1) * STGW;                     // A tile
        const uint32_t* stB = dsm + (i & 1) * STGW + 4096 + (wn << 11); // B half
#pragma unroll
        for (int s = 0; s < 4; s++) {                     // 4 k16-steps per chunk
            uint4 af[4], bv[4];
#pragma unroll
            for (int mt = 0; mt < 4; mt++)
                af[mt] = *(const uint4*)&stA[(((wm << 2) + mt) << 9) + (s << 7) +
                                             (grp << 4) + (qid << 2)];
#pragma unroll
            for (int np = 0; np < 4; np++)
                bv[np] = *(const uint4*)&stB[(np << 9) + (s << 7) + (grp << 4) + (qid << 2)];
#pragma unroll
            for (int mt = 0; mt < 4; mt++)
#pragma unroll
                for (int np = 0; np < 4; np++) {
                    asm volatile(
                        "mma.sync.aligned.m16n8k16.row.col.f32.f16.f16.f32 "
                        "{%0,%1,%2,%3}, {%4,%5,%6,%7}, {%8,%9}, {%0,%1,%2,%3};"
                        : "+f"(acc[mt][2*np][0]), "+f"(acc[mt][2*np][1]),
                          "+f"(acc[mt][2*np][2]), "+f"(acc[mt][2*np][3])
                        : "r"(af[mt].x), "r"(af[mt].y), "r"(af[mt].z), "r"(af[mt].w),
                          "r"(bv[np].x), "r"(bv[np].y));
                    asm volatile(
                        "mma.sync.aligned.m16n8k16.row.col.f32.f16.f16.f32 "
                        "{%0,%1,%2,%3}, {%4,%5,%6,%7}, {%8,%9}, {%0,%1,%2,%3};"
                        : "+f"(acc[mt][2*np+1][0]), "+f"(acc[mt][2*np+1][1]),
                          "+f"(acc[mt][2*np+1][2]), "+f"(acc[mt][2*np+1][3])
                        : "r"(af[mt].x), "r"(af[mt].y), "r"(af[mt].z), "r"(af[mt].w),
                          "r"(bv[np].z), "r"(bv[np].w));
                }
        }
    }

    // --- epilogue ---
    const int m0 = mblk * 128 + wm * 64, n0 = nblk * 128 + wn * 64;
#pragma unroll
    for (int mt = 0; mt < 4; mt++)
#pragma unroll
        for (int nt = 0; nt < 8; nt++) {
            const int row = m0 + mt * 16 + grp;
            const int col = n0 + (nt << 3) + (qid << 1);   // even
            float o0 = acc[mt][nt][0], o1 = acc[mt][nt][1];
            float o2 = acc[mt][nt][2], o3 = acc[mt][nt][3];
            if (ISOUT) {
                *(float2*)(Yout + (size_t)row * CC + col)       = make_float2(o0, o1);
                *(float2*)(Yout + (size_t)(row + 8) * CC + col) = make_float2(o2, o3);
            } else {
                if (z == 2) {
                    o0 = 1.f / (1.f + __expf(-o0));
                    o1 = 1.f / (1.f + __expf(-o1));
                    o2 = 1.f / (1.f + __expf(-o2));
                    o3 = 1.f / (1.f + __expf(-o3));
                }
                Y16[(size_t)row * CP2 + (col >> 1)]       = pack_h2(o0, o1);
                Y16[(size_t)(row + 8) * CP2 + (col >> 1)] = pack_h2(o2, o3);
            }
        }
}

// ---------------------------------------------------------------------------
// WKV chunked parallel scan over packed half2 k/v/r.
// One thread per CHANNEL PAIR; NCH=64 chunks of 64 steps.
// ---------------------------------------------------------------------------
__global__ void __launch_bounds__(256) scan_states(const float* __restrict__ td)
{
    const int bid   = blockIdx.x;            // 512 blocks = 4 b x 64 chunk x 2 pg
    const int b     = bid >> 7;
    const int chunk = (bid >> 1) & 63;
    const int pair  = ((bid & 1) << 8) + threadIdx.x;   // [0, 512)
    const int c0    = pair << 1;

    const float w0 = expf(td[c0]), w1 = expf(td[c0 + 1]);
    const size_t base = (size_t)(b * TT + chunk * CLEN) * CP2 + pair;

    float aa0 = 0.f, bb0 = 0.f, pp0 = -1e38f;
    float aa1 = 0.f, bb1 = 0.f, pp1 = -1e38f;
#pragma unroll 4
    for (int t = 0; t < CLEN; t++) {
        const float2 kt = unpack_h2(g_k16[base + (size_t)t * CP2]);
        const float2 vt = unpack_h2(g_v16[base + (size_t)t * CP2]);
        {
            const float ww2 = pp0 - w0;
            const float p2  = fmaxf(ww2, kt.x);
            const float e1b = __expf(ww2 - p2);
            const float e2b = __expf(kt.x - p2);
            aa0 = e1b * aa0 + e2b * vt.x;
            bb0 = e1b * bb0 + e2b;
            pp0 = p2;
        }
        {
            const float ww2 = pp1 - w1;
            const float p2  = fmaxf(ww2, kt.y);
            const float e1b = __expf(ww2 - p2);
            const float e2b = __expf(kt.y - p2);
            aa1 = e1b * aa1 + e2b * vt.y;
            bb1 = e1b * bb1 + e2b;
            pp1 = p2;
        }
    }
    const int i = b * CC + c0;
    *(float2*)&g_saa[chunk][i] = make_float2(aa0, aa1);
    *(float2*)&g_sbb[chunk][i] = make_float2(bb0, bb1);
    *(float2*)&g_spp[chunk][i] = make_float2(pp0, pp1);
}

// ---------------------------------------------------------------------------
// Kogge-Stone combine over the 64 chunks (log-depth, was sequential).
// Block = 64 chunks x 16 channels = 1024 threads; 256 blocks cover NBC=4096.
// Merge op is associative on the unnormalized state (aa*e^pp, bb*e^pp);
// at offset o the right operand spans exactly o chunks -> decay = o*CLEN*w.
// ---------------------------------------------------------------------------
__global__ void __launch_bounds__(1024) scan_combine(const float* __restrict__ td,
                                                     const float* __restrict__ aa0,
                                                     const float* __restrict__ bb0,
                                                     const float* __restrict__ pp0)
{
    __shared__ float s_aa[1024], s_bb[1024], s_pp[1024];

    const int tid = threadIdx.x;
    const int ch  = tid >> 4;                 // chunk [0,64)
    const int q   = tid & 15;                 // channel lane within block
    const int i   = blockIdx.x * 16 + q;      // [0, 4096)
    const int c   = i & (CC - 1);
    const float w = expf(td[c]);

    float aa = g_saa[ch][i], bb = g_sbb[ch][i], pp = g_spp[ch][i];
    s_aa[tid] = aa; s_bb[tid] = bb; s_pp[tid] = pp;
    __syncthreads();

#pragma unroll
    for (int o = 1; o < NCH; o <<= 1) {
        float xaa, xbb, xpp;
        const bool act = (ch >= o);
        if (act) {
            xaa = s_aa[tid - (o << 4)];
            xbb = s_bb[tid - (o << 4)];
            xpp = s_pp[tid - (o << 4)];
        }
        __syncthreads();
        if (act) {
            const float dec = (float)(o * CLEN) * w;
            const float xp  = xpp - dec;
            const float p   = fmaxf(xp, pp);
            const float e1  = __expf(xp - p);
            const float e2  = __expf(pp - p);
            aa = e1 * xaa + e2 * aa;
            bb = e1 * xbb + e2 * bb;
            pp = p;
            s_aa[tid] = aa; s_bb[tid] = bb; s_pp[tid] = pp;
        }
        __syncthreads();
    }

    // exclusive output: incoming state for chunk ch = merge(seed, I[ch-1])
    const float paa = aa0[i], pbb = bb0[i], ppp = pp0[i];
    if (ch == 0) {
        g_iaa[0][i] = paa; g_ibb[0][i] = pbb; g_ipp[0][i] = ppp;
    } else {
        const float dec = (float)(ch * CLEN) * w;
        const float xp  = ppp - dec;
        const float Iaa = s_aa[tid - 16], Ibb = s_bb[tid - 16], Ipp = s_pp[tid - 16];
        const float p   = fmaxf(xp, Ipp);
        const float e1  = __expf(xp - p);
        const float e2  = __expf(Ipp - p);
        g_iaa[ch][i] = e1 * paa + e2 * Iaa;
        g_ibb[ch][i] = e1 * pbb + e2 * Ibb;
        g_ipp[ch][i] = p;
    }
}

__global__ void __launch_bounds__(256) scan_out(const float* __restrict__ td,
                                                const float* __restrict__ tf,
                                                float* __restrict__ out_tail)
{
    const int bid   = blockIdx.x;            // 512 blocks
    const int b     = bid >> 7;
    const int chunk = (bid >> 1) & 63;
    const int pair  = ((bid & 1) << 8) + threadIdx.x;   // [0, 512)
    const int c0    = pair << 1;
    const int i     = b * CC + c0;

    const float w0 = expf(td[c0]), w1 = expf(td[c0 + 1]);
    const float u0 = tf[c0],       u1 = tf[c0 + 1];
    float2 aa = *(const float2*)&g_iaa[chunk][i];
    float2 bb = *(const float2*)&g_ibb[chunk][i];
    float2 pp = *(const float2*)&g_ipp[chunk][i];

    const size_t base = (size_t)(b * TT + chunk * CLEN) * CP2 + pair;
    const int mbase = b * TT + chunk * CLEN;

    // strength-reduced a16_idx: a 64-step chunk never crosses an mblk
    // boundary (mbase % 64 == 0), and the pair-dependent K-part is constant.
    const int pq = pair & 31, kblk = pair >> 5;
    const size_t tile0 = (size_t)((mbase >> 7) * 16 + kblk) * 4096 +
                         ((pq >> 3) << 7) + ((pq & 3) << 2) + (((pq >> 2) & 1) << 1);
    const int r0 = mbase & 127;

#pragma unroll 4
    for (int t = 0; t < CLEN; t++) {
        const float2 kt = unpack_h2(g_k16[base + (size_t)t * CP2]);
        const float2 vt = unpack_h2(g_v16[base + (size_t)t * CP2]);
        const float2 rt = unpack_h2(g_r16[base + (size_t)t * CP2]);
        float wkv0, wkv1;
        {
            const float ww = u0 + kt.x;
            const float p  = fmaxf(pp.x, ww);
            const float e1 = __expf(pp.x - p);
            const float e2 = __expf(ww - p);
            wkv0 = __fdividef(e1 * aa.x + e2 * vt.x, e1 * bb.x + e2);
            const float ww2 = pp.x - w0;
            const float p2  = fmaxf(ww2, kt.x);
            const float e1b = __expf(ww2 - p2);
            const float e2b = __expf(kt.x - p2);
            aa.x = e1b * aa.x + e2b * vt.x;
            bb.x = e1b * bb.x + e2b;
            pp.x = p2;
        }
        {
            const float ww = u1 + kt.y;
            const float p  = fmaxf(pp.y, ww);
            const float e1 = __expf(pp.y - p);
            const float e2 = __expf(ww - p);
            wkv1 = __fdividef(e1 * aa.y + e2 * vt.y, e1 * bb.y + e2);
            const float ww2 = pp.y - w1;
            const float p2  = fmaxf(ww2, kt.y);
            const float e1b = __expf(ww2 - p2);
            const float e2b = __expf(kt.y - p2);
            aa.y = e1b * aa.y + e2b * vt.y;
            bb.y = e1b * bb.y + e2b;
            pp.y = p2;
        }
        const int r = r0 + t;
        g_wkv16[tile0 + ((r >> 4) << 9) + ((r & 7) << 4) + ((r >> 3) & 1)] =
            pack_h2(rt.x * wkv0, rt.y * wkv1);
    }

    if (chunk == NCH - 1) {
        *(float2*)(out_tail + i)           = aa;
        *(float2*)(out_tail + NBC + i)     = bb;
        *(float2*)(out_tail + 2 * NBC + i) = pp;
    }
}

// ---------------------------------------------------------------------------
// Launch
// ---------------------------------------------------------------------------
extern "C" void kernel_launch(void* const* d_in, const int* in_sizes, int n_in,
                              void* d_out, int out_size)
{
    const float* x    = (const float*)d_in[0];
    const float* kw   = (const float*)d_in[1];
    const float* vw   = (const float*)d_in[2];
    const float* rw   = (const float*)d_in[3];
    const float* ow   = (const float*)d_in[4];
    const float* td   = (const float*)d_in[5];
    const float* tf   = (const float*)d_in[6];
    const float* aa0  = (const float*)d_in[7];
    const float* bb0  = (const float*)d_in[8];
    const float* pp0  = (const float*)d_in[9];

    float* out  = (float*)d_out;
    float* tail = out + (size_t)BTC;

    static bool configured = false;
    if (!configured) {
        cudaFuncSetAttribute(gemm_mm<false>, cudaFuncAttributeMaxDynamicSharedMemorySize,
                             STAGES * STGB);
        cudaFuncSetAttribute(gemm_mm<true>,  cudaFuncAttributeMaxDynamicSharedMemorySize,
                             STAGES * STGB);
        configured = true;
    }

    // fused pre-pass: fp16-round + fragment-permute x and weights
    round_all<<<1536, 256>>>(x, kw, vw, rw, ow);

    // fused k/v/r projections (fp16 packed outputs)
    gemm_mm<false><<<dim3(8, 128, 3), 128, STAGES * STGB>>>(nullptr);

    // chunked parallel WKV scan (channel-pair threads, 64 chunks)
    scan_states<<<512, 256>>>(td);
    scan_combine<<<256, 1024>>>(td, aa0, bb0, pp0);
    scan_out<<<512, 256>>>(td, tf, tail);

    // out = (r * wkv) @ ow^T  (A pre-multiplied, packed, permuted by scan_out)
    gemm_mm<true><<<dim3(8, 128, 1), 128, STAGES * STGB>>>(out);
}

// round 17
// speedup vs baseline: 1.0919x; 1.0082x over previous
#include <cuda_runtime.h>
#include <cuda_fp16.h>
#include <cstdint>
#include <cstddef>

// Problem sizes (fixed)
#define BB 4
#define TT 4096
#define CC 1024
#define MM (BB * TT)          // 16384
#define BTC (BB * TT * CC)    // 16,777,216
#define NCH 64                // scan chunks along T
#define CLEN (TT / NCH)       // 64
#define NBC (BB * CC)         // 4096
#define WSZ (CC * CC)         // 1,048,576
#define CP2 (CC / 2)          // 512 channel pairs

// ---------------------------------------------------------------------------
// Scratch in device globals (no cudaMalloc allowed).
// ---------------------------------------------------------------------------
__device__ __align__(16) uint32_t g_k16[BTC / 2];
__device__ __align__(16) uint32_t g_v16[BTC / 2];
__device__ __align__(16) uint32_t g_r16[BTC / 2];
__device__ __align__(16) uint32_t g_x16[BTC / 2];     // permuted fp16 x
__device__ __align__(16) uint32_t g_wkv16[BTC / 2];   // permuted fp16 (r*wkv)
__device__ __align__(16) uint32_t g_wk16[WSZ / 2], g_wv16[WSZ / 2],
                                  g_wr16[WSZ / 2], g_wo16[WSZ / 2];
__device__ float g_saa[NCH][NBC], g_sbb[NCH][NBC], g_spp[NCH][NBC];
__device__ float g_iaa[NCH][NBC], g_ibb[NCH][NBC], g_ipp[NCH][NBC];

// ---------------------------------------------------------------------------
// Helpers
// ---------------------------------------------------------------------------
__device__ __forceinline__ uint32_t smem_u32(const void* p) {
    return (uint32_t)__cvta_generic_to_shared(p);
}
__device__ __forceinline__ void cp16(uint32_t smem_dst, const void* gmem_src) {
    asm volatile("cp.async.cg.shared.global [%0], [%1], 16;\n" :: "r"(smem_dst), "l"(gmem_src));
}
__device__ __forceinline__ void cp_commit() { asm volatile("cp.async.commit_group;\n"); }
template<int N>
__device__ __forceinline__ void cp_wait() { asm volatile("cp.async.wait_group %0;\n" :: "n"(N)); }

__device__ __forceinline__ uint32_t pack_h2(float lo, float hi) {
    const __half2 h = __floats2half2_rn(lo, hi);   // lo -> low 16 bits
    return *(const uint32_t*)&h;
}
__device__ __forceinline__ float2 unpack_h2(uint32_t w) {
    return __half22float2(*(const __half2*)&w);
}

// A-side permuted layout over half2 words (p = k>>1). Tiles of 128 m x 32 p.
__device__ __forceinline__ size_t a16_idx(int m, int p) {
    const int mblk = m >> 7, kblk = p >> 5, r = m & 127, pq = p & 31;
    return (size_t)(mblk * 16 + kblk) * 4096 +
           ((r >> 4) << 9) + ((pq >> 3) << 7) + ((r & 7) << 4) +
           ((pq & 3) << 2) + (((pq >> 2) & 1) << 1) + ((r >> 3) & 1);
}
// B-side PAIR-PACKED layout: tiles of 64 n x 32 p.
__device__ __forceinline__ size_t b16_idx(int n, int p) {
    const int nblk = n >> 6, kblk = p >> 5, r = n & 63, pq = p & 31;
    const int nt = r >> 3;
    return (size_t)(nblk * 16 + kblk) * 2048 +
           ((nt >> 1) << 9) + ((pq >> 3) << 7) + ((r & 7) << 4) +
           ((pq & 3) << 2) + ((nt & 1) << 1) + ((pq >> 2) & 1);
}

// ---------------------------------------------------------------------------
// Fused pre-pass: fp16-round + fragment-permute x and all 4 weights.
// Blocks [0,1024) handle x; blocks [1024,1536) handle weights (128 per weight).
// ---------------------------------------------------------------------------
__global__ void __launch_bounds__(256) round_all(const float* __restrict__ x,
                                                 const float* __restrict__ kw,
                                                 const float* __restrict__ vw,
                                                 const float* __restrict__ rw,
                                                 const float* __restrict__ ow)
{
    const int bx = blockIdx.x;
    if (bx < 1024) {
        const int n4 = BTC / 4;
        for (int f = bx * 256 + threadIdx.x; f < n4; f += 1024 * 256) {
            const int m = f >> 8, c0 = (f & 255) << 2;
            const float4 v = ((const float4*)x)[f];
            const size_t base = a16_idx(m, c0 >> 1);
            g_x16[base]     = pack_h2(v.x, v.y);
            g_x16[base + 4] = pack_h2(v.z, v.w);
        }
    } else {
        const int wb = bx - 1024;            // [0, 512)
        const int z  = wb >> 7;              // 128 blocks per weight
        const float* src = z == 0 ? kw : (z == 1 ? vw : (z == 2 ? rw : ow));
        uint32_t* dst    = z == 0 ? g_wk16 : (z == 1 ? g_wv16 : (z == 2 ? g_wr16 : g_wo16));
        const int n4 = WSZ / 4;
        for (int f = (wb & 127) * 256 + threadIdx.x; f < n4; f += 128 * 256) {
            const int n = f >> 8, c0 = (f & 255) << 2;
            const float4 v = ((const float4*)src)[f];
            const size_t base = b16_idx(n, c0 >> 1);
            dst[base]     = pack_h2(v.x, v.y);
            dst[base + 4] = pack_h2(v.z, v.w);
        }
    }
}

// ---------------------------------------------------------------------------
// FP16 mma.sync GEMM (m16n8k16), cp.async 2-stage pipeline.
// Projections (ISOUT=false): tile 128x128, 3 CTAs/SM.
// OUT        (ISOUT=true):   tile 128x64,  4 CTAs/SM (kills wave-quant tail).
// 4 warps in 2(M) x 2(N) grid; warp tile 64 x (BN/2).
// ---------------------------------------------------------------------------
#define STAGES 2
#define NKC 16               // 1024 / 64

template<bool ISOUT>
__global__ void __launch_bounds__(128, ISOUT ? 4 : 3) gemm_mm(float* __restrict__ Yout)
{
    constexpr int BN    = ISOUT ? 64 : 128;   // block N tile
    constexpr int BHALF = BN / 64;            // 64-col B tiles per block
    constexpr int NPW   = BN / 32;            // uint4 B-groups per warp per step
    constexpr int NT    = BN / 16;            // n8-frags per warp
    constexpr int STGW  = 4096 + BHALF * 2048;   // words per stage

    extern __shared__ __align__(16) uint32_t dsm[];

    const int z = blockIdx.z;
    const uint32_t* A = ISOUT ? g_wkv16 : g_x16;
    const uint32_t* W = ISOUT ? g_wo16 : (z == 0 ? g_wk16 : (z == 1 ? g_wv16 : g_wr16));
    uint32_t* Y16     = ISOUT ? nullptr : (z == 0 ? g_k16 : (z == 1 ? g_v16 : g_r16));

    const int tid  = threadIdx.x;
    const int warp = tid >> 5, lane = tid & 31;
    const int mblk = blockIdx.y, nblk = blockIdx.x;   // 128-row, BN-col tiles
    const int wm   = warp & 1;          // 2 warps cover M (64 rows each)
    const int wn   = warp >> 1;         // 2 warps cover N (BN/2 cols each)
    const int grp  = lane >> 2, qid = lane & 3;

    const uint32_t sbase = smem_u32(dsm);

    auto load_stage = [&](int slot, int kblk) {
        const uint32_t sb = sbase + slot * (STGW * 4);
        const uint32_t* at = A + (size_t)(mblk * 16 + kblk) * 4096;
#pragma unroll
        for (int i = 0; i < 8; i++) {               // 1024 A 16B-chunks
            const int ch = tid + (i << 7);
            cp16(sb + ch * 16, at + ch * 4);
        }
#pragma unroll
        for (int h = 0; h < BHALF; h++) {           // 64-col B halves
            const uint32_t* bt = W + (size_t)((nblk * BHALF + h) * 16 + kblk) * 2048;
#pragma unroll
            for (int i = 0; i < 4; i++) {           // 512 chunks per half
                const int ch = tid + (i << 7);
                cp16(sb + 16384 + h * 8192 + ch * 16, bt + ch * 4);
            }
        }
    };

    float acc[4][NT][4];
#pragma unroll
    for (int a = 0; a < 4; a++)
#pragma unroll
        for (int b = 0; b < NT; b++)
#pragma unroll
            for (int c = 0; c < 4; c++) acc[a][b][c] = 0.f;

    load_stage(0, 0); cp_commit();

    for (int i = 0; i < NKC; i++) {
        cp_wait<0>();            // chunk i resident in slot i&1
        __syncthreads();         // everyone done with slot (i+1)&1 (chunk i-1)
        if (i + 1 < NKC) { load_stage((i + 1) & 1, i + 1); cp_commit(); }

        const uint32_t* stA = dsm + (i & 1) * STGW;            // A tile
        const uint32_t* stB = dsm + (i & 1) * STGW + 4096;     // B tiles
#pragma unroll
        for (int s = 0; s < 4; s++) {                     // 4 k16-steps per chunk
            uint4 af[4], bv[NPW];
#pragma unroll
            for (int mt = 0; mt < 4; mt++)
                af[mt] = *(const uint4*)&stA[(((wm << 2) + mt) << 9) + (s << 7) +
                                             (grp << 4) + (qid << 2)];
#pragma unroll
            for (int np = 0; np < NPW; np++) {
                const int gnp = wn * NPW + np;        // global uint4-group
                bv[np] = *(const uint4*)&stB[(gnp << 9) + (s << 7) + (grp << 4) + (qid << 2)];
            }
#pragma unroll
            for (int mt = 0; mt < 4; mt++)
#pragma unroll
                for (int np = 0; np < NPW; np++) {
                    asm volatile(
                        "mma.sync.aligned.m16n8k16.row.col.f32.f16.f16.f32 "
                        "{%0,%1,%2,%3}, {%4,%5,%6,%7}, {%8,%9}, {%0,%1,%2,%3};"
                        : "+f"(acc[mt][2*np][0]), "+f"(acc[mt][2*np][1]),
                          "+f"(acc[mt][2*np][2]), "+f"(acc[mt][2*np][3])
                        : "r"(af[mt].x), "r"(af[mt].y), "r"(af[mt].z), "r"(af[mt].w),
                          "r"(bv[np].x), "r"(bv[np].y));
                    asm volatile(
                        "mma.sync.aligned.m16n8k16.row.col.f32.f16.f16.f32 "
                        "{%0,%1,%2,%3}, {%4,%5,%6,%7}, {%8,%9}, {%0,%1,%2,%3};"
                        : "+f"(acc[mt][2*np+1][0]), "+f"(acc[mt][2*np+1][1]),
                          "+f"(acc[mt][2*np+1][2]), "+f"(acc[mt][2*np+1][3])
                        : "r"(af[mt].x), "r"(af[mt].y), "r"(af[mt].z), "r"(af[mt].w),
                          "r"(bv[np].z), "r"(bv[np].w));
                }
        }
    }

    // --- epilogue ---
    const int m0 = mblk * 128 + wm * 64, n0 = nblk * BN + wn * (BN / 2);
#pragma unroll
    for (int mt = 0; mt < 4; mt++)
#pragma unroll
        for (int nt = 0; nt < NT; nt++) {
            const int row = m0 + mt * 16 + grp;
            const int col = n0 + (nt << 3) + (qid << 1);   // even
            float o0 = acc[mt][nt][0], o1 = acc[mt][nt][1];
            float o2 = acc[mt][nt][2], o3 = acc[mt][nt][3];
            if (ISOUT) {
                *(float2*)(Yout + (size_t)row * CC + col)       = make_float2(o0, o1);
                *(float2*)(Yout + (size_t)(row + 8) * CC + col) = make_float2(o2, o3);
            } else {
                if (z == 2) {
                    o0 = 1.f / (1.f + __expf(-o0));
                    o1 = 1.f / (1.f + __expf(-o1));
                    o2 = 1.f / (1.f + __expf(-o2));
                    o3 = 1.f / (1.f + __expf(-o3));
                }
                Y16[(size_t)row * CP2 + (col >> 1)]       = pack_h2(o0, o1);
                Y16[(size_t)(row + 8) * CP2 + (col >> 1)] = pack_h2(o2, o3);
            }
        }
}

// ---------------------------------------------------------------------------
// WKV chunked parallel scan over packed half2 k/v/r.
// One thread per CHANNEL PAIR; NCH=64 chunks of 64 steps.
// ---------------------------------------------------------------------------
__global__ void __launch_bounds__(256) scan_states(const float* __restrict__ td)
{
    const int bid   = blockIdx.x;            // 512 blocks = 4 b x 64 chunk x 2 pg
    const int b     = bid >> 7;
    const int chunk = (bid >> 1) & 63;
    const int pair  = ((bid & 1) << 8) + threadIdx.x;   // [0, 512)
    const int c0    = pair << 1;

    const float w0 = expf(td[c0]), w1 = expf(td[c0 + 1]);
    const size_t base = (size_t)(b * TT + chunk * CLEN) * CP2 + pair;

    float aa0 = 0.f, bb0 = 0.f, pp0 = -1e38f;
    float aa1 = 0.f, bb1 = 0.f, pp1 = -1e38f;
#pragma unroll 4
    for (int t = 0; t < CLEN; t++) {
        const float2 kt = unpack_h2(g_k16[base + (size_t)t * CP2]);
        const float2 vt = unpack_h2(g_v16[base + (size_t)t * CP2]);
        {
            const float ww2 = pp0 - w0;
            const float p2  = fmaxf(ww2, kt.x);
            const float e1b = __expf(ww2 - p2);
            const float e2b = __expf(kt.x - p2);
            aa0 = e1b * aa0 + e2b * vt.x;
            bb0 = e1b * bb0 + e2b;
            pp0 = p2;
        }
        {
            const float ww2 = pp1 - w1;
            const float p2  = fmaxf(ww2, kt.y);
            const float e1b = __expf(ww2 - p2);
            const float e2b = __expf(kt.y - p2);
            aa1 = e1b * aa1 + e2b * vt.y;
            bb1 = e1b * bb1 + e2b;
            pp1 = p2;
        }
    }
    const int i = b * CC + c0;
    *(float2*)&g_saa[chunk][i] = make_float2(aa0, aa1);
    *(float2*)&g_sbb[chunk][i] = make_float2(bb0, bb1);
    *(float2*)&g_spp[chunk][i] = make_float2(pp0, pp1);
}

// ---------------------------------------------------------------------------
// Kogge-Stone combine over the 64 chunks (log-depth).
// Block = 64 chunks x 16 channels = 1024 threads; 256 blocks cover NBC=4096.
// ---------------------------------------------------------------------------
__global__ void __launch_bounds__(1024) scan_combine(const float* __restrict__ td,
                                                     const float* __restrict__ aa0,
                                                     const float* __restrict__ bb0,
                                                     const float* __restrict__ pp0)
{
    __shared__ float s_aa[1024], s_bb[1024], s_pp[1024];

    const int tid = threadIdx.x;
    const int ch  = tid >> 4;                 // chunk [0,64)
    const int q   = tid & 15;                 // channel lane within block
    const int i   = blockIdx.x * 16 + q;      // [0, 4096)
    const int c   = i & (CC - 1);
    const float w = expf(td[c]);

    float aa = g_saa[ch][i], bb = g_sbb[ch][i], pp = g_spp[ch][i];
    s_aa[tid] = aa; s_bb[tid] = bb; s_pp[tid] = pp;
    __syncthreads();

#pragma unroll
    for (int o = 1; o < NCH; o <<= 1) {
        float xaa, xbb, xpp;
        const bool act = (ch >= o);
        if (act) {
            xaa = s_aa[tid - (o << 4)];
            xbb = s_bb[tid - (o << 4)];
            xpp = s_pp[tid - (o << 4)];
        }
        __syncthreads();
        if (act) {
            const float dec = (float)(o * CLEN) * w;
            const float xp  = xpp - dec;
            const float p   = fmaxf(xp, pp);
            const float e1  = __expf(xp - p);
            const float e2  = __expf(pp - p);
            aa = e1 * xaa + e2 * aa;
            bb = e1 * xbb + e2 * bb;
            pp = p;
            s_aa[tid] = aa; s_bb[tid] = bb; s_pp[tid] = pp;
        }
        __syncthreads();
    }

    // exclusive output: incoming state for chunk ch = merge(seed, I[ch-1])
    const float paa = aa0[i], pbb = bb0[i], ppp = pp0[i];
    if (ch == 0) {
        g_iaa[0][i] = paa; g_ibb[0][i] = pbb; g_ipp[0][i] = ppp;
    } else {
        const float dec = (float)(ch * CLEN) * w;
        const float xp  = ppp - dec;
        const float Iaa = s_aa[tid - 16], Ibb = s_bb[tid - 16], Ipp = s_pp[tid - 16];
        const float p   = fmaxf(xp, Ipp);
        const float e1  = __expf(xp - p);
        const float e2  = __expf(Ipp - p);
        g_iaa[ch][i] = e1 * paa + e2 * Iaa;
        g_ibb[ch][i] = e1 * pbb + e2 * Ibb;
        g_ipp[ch][i] = p;
    }
}

__global__ void __launch_bounds__(256) scan_out(const float* __restrict__ td,
                                                const float* __restrict__ tf,
                                                float* __restrict__ out_tail)
{
    const int bid   = blockIdx.x;            // 512 blocks
    const int b     = bid >> 7;
    const int chunk = (bid >> 1) & 63;
    const int pair  = ((bid & 1) << 8) + threadIdx.x;   // [0, 512)
    const int c0    = pair << 1;
    const int i     = b * CC + c0;

    const float w0 = expf(td[c0]), w1 = expf(td[c0 + 1]);
    const float u0 = tf[c0],       u1 = tf[c0 + 1];
    float2 aa = *(const float2*)&g_iaa[chunk][i];
    float2 bb = *(const float2*)&g_ibb[chunk][i];
    float2 pp = *(const float2*)&g_ipp[chunk][i];

    const size_t base = (size_t)(b * TT + chunk * CLEN) * CP2 + pair;
    const int mbase = b * TT + chunk * CLEN;

    // strength-reduced a16_idx: a 64-step chunk never crosses an mblk
    // boundary (mbase % 64 == 0), and the pair-dependent K-part is constant.
    const int pq = pair & 31, kblk = pair >> 5;
    const size_t tile0 = (size_t)((mbase >> 7) * 16 + kblk) * 4096 +
                         ((pq >> 3) << 7) + ((pq & 3) << 2) + (((pq >> 2) & 1) << 1);
    const int r0 = mbase & 127;

#pragma unroll 8
    for (int t = 0; t < CLEN; t++) {
        const float2 kt = unpack_h2(g_k16[base + (size_t)t * CP2]);
        const float2 vt = unpack_h2(g_v16[base + (size_t)t * CP2]);
        const float2 rt = unpack_h2(g_r16[base + (size_t)t * CP2]);
        float wkv0, wkv1;
        {
            const float ww = u0 + kt.x;
            const float p  = fmaxf(pp.x, ww);
            const float e1 = __expf(pp.x - p);
            const float e2 = __expf(ww - p);
            wkv0 = __fdividef(e1 * aa.x + e2 * vt.x, e1 * bb.x + e2);
            const float ww2 = pp.x - w0;
            const float p2  = fmaxf(ww2, kt.x);
            const float e1b = __expf(ww2 - p2);
            const float e2b = __expf(kt.x - p2);
            aa.x = e1b * aa.x + e2b * vt.x;
            bb.x = e1b * bb.x + e2b;
            pp.x = p2;
        }
        {
            const float ww = u1 + kt.y;
            const float p  = fmaxf(pp.y, ww);
            const float e1 = __expf(pp.y - p);
            const float e2 = __expf(ww - p);
            wkv1 = __fdividef(e1 * aa.y + e2 * vt.y, e1 * bb.y + e2);
            const float ww2 = pp.y - w1;
            const float p2  = fmaxf(ww2, kt.y);
            const float e1b = __expf(ww2 - p2);
            const float e2b = __expf(kt.y - p2);
            aa.y = e1b * aa.y + e2b * vt.y;
            bb.y = e1b * bb.y + e2b;
            pp.y = p2;
        }
        const int r = r0 + t;
        g_wkv16[tile0 + ((r >> 4) << 9) + ((r & 7) << 4) + ((r >> 3) & 1)] =
            pack_h2(rt.x * wkv0, rt.y * wkv1);
    }

    if (chunk == NCH - 1) {
        *(float2*)(out_tail + i)           = aa;
        *(float2*)(out_tail + NBC + i)     = bb;
        *(float2*)(out_tail + 2 * NBC + i) = pp;
    }
}

// ---------------------------------------------------------------------------
// Launch
// ---------------------------------------------------------------------------
extern "C" void kernel_launch(void* const* d_in, const int* in_sizes, int n_in,
                              void* d_out, int out_size)
{
    const float* x    = (const float*)d_in[0];
    const float* kw   = (const float*)d_in[1];
    const float* vw   = (const float*)d_in[2];
    const float* rw   = (const float*)d_in[3];
    const float* ow   = (const float*)d_in[4];
    const float* td   = (const float*)d_in[5];
    const float* tf   = (const float*)d_in[6];
    const float* aa0  = (const float*)d_in[7];
    const float* bb0  = (const float*)d_in[8];
    const float* pp0  = (const float*)d_in[9];

    float* out  = (float*)d_out;
    float* tail = out + (size_t)BTC;

    const int smem_proj = STAGES * (4096 + 2 * 2048) * 4;   // 65536 B
    const int smem_out  = STAGES * (4096 + 1 * 2048) * 4;   // 49152 B

    static bool configured = false;
    if (!configured) {
        cudaFuncSetAttribute(gemm_mm<false>, cudaFuncAttributeMaxDynamicSharedMemorySize,
                             smem_proj);
        cudaFuncSetAttribute(gemm_mm<true>,  cudaFuncAttributeMaxDynamicSharedMemorySize,
                             smem_out);
        configured = true;
    }

    // fused pre-pass: fp16-round + fragment-permute x and weights
    round_all<<<1536, 256>>>(x, kw, vw, rw, ow);

    // fused k/v/r projections (fp16 packed outputs), 128x128 tiles
    gemm_mm<false><<<dim3(8, 128, 3), 128, smem_proj>>>(nullptr);

    // chunked parallel WKV scan (channel-pair threads, 64 chunks)
    scan_states<<<512, 256>>>(td);
    scan_combine<<<256, 1024>>>(td, aa0, bb0, pp0);
    scan_out<<<512, 256>>>(td, tf, tail);

    // out = (r * wkv) @ ow^T, 128x64 tiles, 4 CTAs/SM (reduced wave tail)
    gemm_mm<true><<<dim3(16, 128, 1), 128, smem_out>>>(out);
}